// round 5
// baseline (speedup 1.0000x reference)
#include <cuda_runtime.h>
#include <cuda_bf16.h>
#include <cstdint>

// RNN-T joint network, 2 launches:
//  1) convert: fp32 -> bf16 (hi,lo) split images; block 0 also zeroes flags.
//  2) fused:   producer/consumer kernel. Blocks are either GEMM tiles
//     (mma.sync bf16, 64x128 tile, BK=64, 3-stage cp.async, SW128) that
//     publish projection tiles via release flags, or ADD blocks that
//     acquire-wait on their one enc tile + one pred tile and stream 1 MB of
//     output each (st.global.cs). Output drain overlaps GEMM compute.

#define VOCAB 2048
#define KC    1536
#define NB    4
#define NT    256
#define NU    64

// -------- scratch (device globals; no allocations allowed) --------
__device__ __nv_bfloat16 g_Ac[1280 * KC];
__device__ __nv_bfloat16 g_Be[VOCAB * KC];
__device__ __nv_bfloat16 g_Bp[VOCAB * KC];
__device__ float g_enc [1024 * VOCAB];
__device__ float g_pred[ 256 * VOCAB];
__device__ int   g_flag_pred[64];     // pred tile (pb, n): idx pb*16+n
__device__ int   g_flag_enc [256];    // enc tile  (m, n):  idx m*16+n

// ---------------------------------------------------------------------------
// Stage 1: split-precision convert (proven; +flag reset in block 0)
// ---------------------------------------------------------------------------
__global__ __launch_bounds__(256)
void convert_kernel(const float* __restrict__ enc,
                    const float* __restrict__ pred,
                    const float* __restrict__ W) {
    if (blockIdx.x == 0) {
        int t = threadIdx.x;
        if (t < 64)  g_flag_pred[t] = 0;
        if (t < 256) g_flag_enc[t]  = 0;
    }
    int idx = blockIdx.x * 256 + threadIdx.x;

    float2 x;
    __nv_bfloat16* base;
    bool isA;
    if (idx < 262144) {
        x = ((const float2*)enc)[idx];
        int m = idx >> 8, k = (idx & 255) * 2;
        base = g_Ac + (size_t)m * KC + k;
        isA = true;
    } else if (idx < 327680) {
        int p = idx - 262144;
        x = ((const float2*)pred)[p];
        int m = 1024 + (p >> 8), k = (p & 255) * 2;
        base = g_Ac + (size_t)m * KC + k;
        isA = true;
    } else {
        int p = idx - 327680;
        x = ((const float2*)W)[p];
        int v = p >> 9, k = (p & 511) * 2;
        if (k < 512) base = g_Be + (size_t)v * KC + k;
        else         base = g_Bp + (size_t)v * KC + (k - 512);
        isA = false;
    }

    __nv_bfloat162 h, l;
    h.x = __float2bfloat16_rn(x.x);
    h.y = __float2bfloat16_rn(x.y);
    l.x = __float2bfloat16_rn(x.x - __bfloat162float(h.x));
    l.y = __float2bfloat16_rn(x.y - __bfloat162float(h.y));

    if (isA) {  // [hi | hi | lo]
        *(__nv_bfloat162*)(base)        = h;
        *(__nv_bfloat162*)(base +  512) = h;
        *(__nv_bfloat162*)(base + 1024) = l;
    } else {    // [hi | lo | hi]
        *(__nv_bfloat162*)(base)        = h;
        *(__nv_bfloat162*)(base +  512) = l;
        *(__nv_bfloat162*)(base + 1024) = h;
    }
}

// ---------------------------------------------------------------------------
// helpers
// ---------------------------------------------------------------------------
#define BK     64
#define STAGES 3
#define A_ST   8192                   // 64 rows * 128B
#define B_ST   16384                  // 128 rows * 128B
#define ST_SZ  (A_ST + B_ST)          // 24KB per stage
#define DSMEM  (STAGES * ST_SZ)       // 72KB (>= 32KB the add path needs)

__device__ __forceinline__ uint32_t s2u(const void* p) {
    return (uint32_t)__cvta_generic_to_shared(p);
}
#define CPA16(s, g) asm volatile("cp.async.cg.shared.global [%0], [%1], 16;" :: "r"(s), "l"(g))
#define LDSM4(r0,r1,r2,r3,a) asm volatile( \
    "ldmatrix.sync.aligned.m8n8.x4.shared.b16 {%0,%1,%2,%3}, [%4];" \
    : "=r"(r0),"=r"(r1),"=r"(r2),"=r"(r3) : "r"(a))
#define MMA16816(c,a0,a1,a2,a3,b0,b1) asm volatile( \
    "mma.sync.aligned.m16n8k16.row.col.f32.bf16.bf16.f32 " \
    "{%0,%1,%2,%3},{%4,%5,%6,%7},{%8,%9},{%0,%1,%2,%3};" \
    : "+f"(c[0]),"+f"(c[1]),"+f"(c[2]),"+f"(c[3]) \
    : "r"(a0),"r"(a1),"r"(a2),"r"(a3),"r"(b0),"r"(b1))

__device__ __forceinline__ uint32_t swz(uint32_t row, uint32_t cb) {
    return row * 128 + (cb ^ ((row & 7) * 16));
}
__device__ __forceinline__ void stcs(float4* p, float4 v) {
    asm volatile("st.global.cs.v4.f32 [%0], {%1,%2,%3,%4};"
                 :: "l"(p), "f"(v.x), "f"(v.y), "f"(v.z), "f"(v.w));
}
__device__ __forceinline__ void wait_flag(const int* f) {
    int v;
    while (true) {
        asm volatile("ld.acquire.gpu.global.b32 %0, [%1];" : "=r"(v) : "l"(f));
        if (v) break;
        __nanosleep(128);
    }
}

// ---------------------------------------------------------------------------
// Fused producer/consumer kernel.
//   bid 0..63        : pred GEMM tile  (pb = bid>>4, n = bid&15)
//   bid 64+3*tri+0   : enc  GEMM tile  (m = tri>>4, n = tri&15)
//   bid 64+3*tri+1,2 : ADD half-blocks for that enc tile
// ---------------------------------------------------------------------------
__global__ __launch_bounds__(256, 2)
void fused_kernel(const float* __restrict__ bias, float* __restrict__ out) {
    extern __shared__ __align__(1024) char smem[];
    const int bid = blockIdx.x;
    const int tid = threadIdx.x;

    if (bid >= 64 && ((bid - 64) % 3) != 0) {
        // ================= ADD flavor =================
        const int tri = (bid - 64) / 3;
        const int r   = (bid - 64) % 3;          // 1 or 2
        const int m   = tri >> 4, n = tri & 15;
        const int b   = m >> 2;
        const int tb  = ((m & 3) << 1) | (r - 1);  // 0..7
        const int vbase = n * 128;
        const int tbase = tb * 32;

        // wait for producers
        if (tid == 0) wait_flag(&g_flag_enc[tri]);
        if (tid == 1) wait_flag(&g_flag_pred[b * 16 + n]);
        __syncthreads();

        float (*ps)[128] = (float(*)[128])smem;   // 64 x 128 fp32 = 32KB
        const float4* pr = (const float4*)(g_pred + (size_t)b * NU * VOCAB + vbase);
        const float4* bi = (const float4*)(bias + vbase);
        #pragma unroll
        for (int i = 0; i < 8; i++) {
            int e = tid + i * 256;
            int u = e >> 5, cc = e & 31;
            float4 p = pr[(size_t)u * (VOCAB / 4) + cc];
            float4 bv = bi[cc];
            ((float4*)ps[u])[cc] =
                make_float4(p.x + bv.x, p.y + bv.y, p.z + bv.z, p.w + bv.w);
        }
        __syncthreads();

        const int w    = tid >> 5;
        const int lane = tid & 31;
        const float4* eb = (const float4*)(g_enc + (size_t)(b * NT + tbase) * VOCAB + vbase);
        float4* ob = (float4*)(out + ((size_t)(b * NT + tbase) * NU) * VOCAB + vbase);

        for (int t = 0; t < 32; t++) {
            float4 e = eb[(size_t)t * (VOCAB / 4) + lane];
            #pragma unroll
            for (int j = 0; j < 8; j++) {
                int u = w * 8 + j;
                float4 p = ((float4*)ps[u])[lane];
                stcs(&ob[((size_t)t * NU + u) * (VOCAB / 4) + lane],
                     make_float4(e.x + p.x, e.y + p.y, e.z + p.z, e.w + p.w));
            }
        }
        return;
    }

    // ================= GEMM flavor =================
    const uint32_t sb = s2u(smem);
    const int lane = tid & 31;
    const int wid  = tid >> 5;
    const int warp_m = wid & 1;
    const int warp_n = wid >> 1;

    int Arow, n, flag_idx;
    const __nv_bfloat16* gBv;
    float* C;
    int* flag;
    if (bid < 64) {
        const int pb = bid >> 4; n = bid & 15;
        Arow = 1024 + pb * 64; gBv = g_Bp;
        C = g_pred + (size_t)(pb * 64) * VOCAB + n * 128;
        flag = &g_flag_pred[bid];
    } else {
        const int tri = (bid - 64) / 3;
        const int m = tri >> 4; n = tri & 15;
        Arow = m * 64; gBv = g_Be;
        C = g_enc + (size_t)(m * 64) * VOCAB + n * 128;
        flag = &g_flag_enc[tri];
    }
    const int vbase = n * 128;
    const __nv_bfloat16* gA = g_Ac + (size_t)Arow * KC;
    const __nv_bfloat16* gB = gBv  + (size_t)vbase * KC;

    const int ca0 = tid, ca1 = tid + 256;
    const int ra0 = ca0 >> 3, ja0 = (ca0 & 7) * 16;
    const int ra1 = ca1 >> 3, ja1 = (ca1 & 7) * 16;
    uint32_t sA0 = swz(ra0, ja0), sA1 = swz(ra1, ja1);
    int      rb[4], jb[4];
    uint32_t sB[4];
    #pragma unroll
    for (int i = 0; i < 4; i++) {
        int cidx = tid + i * 256;
        rb[i] = cidx >> 3; jb[i] = (cidx & 7) * 16;
        sB[i] = swz(rb[i], jb[i]);
    }

    const int rowA = warp_m * 32 + (lane & 15);
    const uint32_t uA = swz(rowA, (lane >> 4) * 16);
    const int rowB = warp_n * 32 + ((lane >> 4) & 1) * 8 + (lane & 7);
    const uint32_t uB = swz(rowB, ((lane >> 3) & 1) * 16);

    float c[2][4][4];
    #pragma unroll
    for (int i = 0; i < 2; i++)
        #pragma unroll
        for (int j = 0; j < 4; j++)
            #pragma unroll
            for (int e = 0; e < 4; e++) c[i][j][e] = 0.f;

    auto fill = [&](int s, int koff) {
        const uint32_t ab = sb + s * ST_SZ;
        const uint32_t bb = ab + A_ST;
        CPA16(ab + sA0, gA + (size_t)ra0 * KC + koff + ja0 / 2);
        CPA16(ab + sA1, gA + (size_t)ra1 * KC + koff + ja1 / 2);
        #pragma unroll
        for (int i = 0; i < 4; i++)
            CPA16(bb + sB[i], gB + (size_t)rb[i] * KC + koff + jb[i] / 2);
        asm volatile("cp.async.commit_group;");
    };

    fill(0, 0);
    fill(1, BK);

    const int NKT = KC / BK;   // 24
    int s = 0;
    for (int kt = 0; kt < NKT; kt++) {
        if (kt < NKT - 1) asm volatile("cp.async.wait_group 1;");
        else              asm volatile("cp.async.wait_group 0;");
        __syncthreads();

        if (kt + 2 < NKT) {
            int sn = s + 2; if (sn >= STAGES) sn -= STAGES;
            fill(sn, (kt + 2) * BK);
        }

        const uint32_t abase = sb + s * ST_SZ + uA;
        const uint32_t bbase = sb + s * ST_SZ + A_ST + uB;
        #pragma unroll
        for (int kk = 0; kk < 4; kk++) {
            uint32_t a[2][4], b[2][4];
            #pragma unroll
            for (int mi = 0; mi < 2; mi++)
                LDSM4(a[mi][0], a[mi][1], a[mi][2], a[mi][3],
                      (abase + mi * 2048) ^ (kk << 5));
            #pragma unroll
            for (int nb = 0; nb < 2; nb++)
                LDSM4(b[nb][0], b[nb][1], b[nb][2], b[nb][3],
                      (bbase + nb * 2048) ^ (kk << 5));
            #pragma unroll
            for (int mi = 0; mi < 2; mi++) {
                MMA16816(c[mi][0], a[mi][0], a[mi][1], a[mi][2], a[mi][3], b[0][0], b[0][1]);
                MMA16816(c[mi][1], a[mi][0], a[mi][1], a[mi][2], a[mi][3], b[0][2], b[0][3]);
                MMA16816(c[mi][2], a[mi][0], a[mi][1], a[mi][2], a[mi][3], b[1][0], b[1][1]);
                MMA16816(c[mi][3], a[mi][0], a[mi][1], a[mi][2], a[mi][3], b[1][2], b[1][3]);
            }
        }
        if (++s >= STAGES) s -= STAGES;
    }

    const int mrow0 = warp_m * 32 + (lane >> 2);
    const int ncol0 = warp_n * 32 + (lane & 3) * 2;
    #pragma unroll
    for (int mi = 0; mi < 2; mi++) {
        #pragma unroll
        for (int ni = 0; ni < 4; ni++) {
            float* p0 = &C[(size_t)(mrow0 + mi * 16)     * VOCAB + ncol0 + ni * 8];
            float* p1 = &C[(size_t)(mrow0 + mi * 16 + 8) * VOCAB + ncol0 + ni * 8];
            *(float2*)p0 = make_float2(c[mi][ni][0], c[mi][ni][1]);
            *(float2*)p1 = make_float2(c[mi][ni][2], c[mi][ni][3]);
        }
    }

    // publish: release the tile
    __threadfence();
    __syncthreads();
    if (tid == 0) atomicExch(flag, 1);
}

// ---------------------------------------------------------------------------
extern "C" void kernel_launch(void* const* d_in, const int* in_sizes, int n_in,
                              void* d_out, int out_size) {
    const float* enc  = (const float*)d_in[0];
    const float* pred = (const float*)d_in[1];
    const float* W    = (const float*)d_in[2];
    const float* bias = (const float*)d_in[3];
    float* out = (float*)d_out;

    cudaFuncSetAttribute(fused_kernel,
                         cudaFuncAttributeMaxDynamicSharedMemorySize, DSMEM);

    convert_kernel<<<5376, 256>>>(enc, pred, W);
    fused_kernel<<<832, 256, DSMEM>>>(bias, out);
}